// round 3
// baseline (speedup 1.0000x reference)
#include <cuda_runtime.h>
#include <cuda_bf16.h>
#include <cstddef>

// Problem constants
#define BATCH 4096
#define NTOK 64            // tokens per window (8x8)
#define CDIM 192
#define NHEAD 6
#define HDIM 32
#define MROWS (BATCH * NTOK)   // 262144
#define QKVW 768               // q(192) + k(192) + v(192) + v_r(192)

// Scratch (device globals; no allocations allowed)
__device__ float g_qkv[(size_t)MROWS * QKVW];   // ~805 MB
__device__ float g_att[(size_t)MROWS * CDIM];   // ~201 MB

// ---------------------------------------------------------------------------
// Generic tiled GEMM:  C[M x Nc] = A[M x K] @ W[K x Nc] + bias
// BM=128, BN=64, BK=16, 128 threads, 8x8 micro-tile per thread.
// A row stride == K. C row stride == ldc. All dims divisible by tile sizes.
// ---------------------------------------------------------------------------
__global__ __launch_bounds__(128) void gemm_bias_kernel(
    const float* __restrict__ A, const float* __restrict__ W,
    const float* __restrict__ bias, float* __restrict__ C,
    int K, int Nc, int ldc)
{
    __shared__ float As[16][128];
    __shared__ float Bs[16][64];

    const int t    = threadIdx.x;
    const int row0 = blockIdx.x * 128;
    const int n0   = blockIdx.y * 64;
    const int tm   = t >> 3;        // 0..15  (8-row group)
    const int tn   = t & 7;         // 0..7   (8-col group)

    float acc[8][8];
#pragma unroll
    for (int i = 0; i < 8; i++)
#pragma unroll
        for (int j = 0; j < 8; j++) acc[i][j] = 0.0f;

    const float* arow = A + (size_t)(row0 + t) * K;
    const int brow = t >> 3;          // 0..15
    const int bcol = (t & 7) * 8;     // 0..56

    for (int k0 = 0; k0 < K; k0 += 16) {
        // Load A tile (128x16), store transposed As[k][m]
#pragma unroll
        for (int i = 0; i < 4; i++) {
            float4 a4 = *(const float4*)(arow + k0 + i * 4);
            As[i * 4 + 0][t] = a4.x;
            As[i * 4 + 1][t] = a4.y;
            As[i * 4 + 2][t] = a4.z;
            As[i * 4 + 3][t] = a4.w;
        }
        // Load B tile (16x64)
        const float* wrow = W + (size_t)(k0 + brow) * Nc + n0 + bcol;
        float4 w0 = *(const float4*)(wrow);
        float4 w1 = *(const float4*)(wrow + 4);
        *(float4*)&Bs[brow][bcol]     = w0;
        *(float4*)&Bs[brow][bcol + 4] = w1;
        __syncthreads();

#pragma unroll
        for (int kk = 0; kk < 16; kk++) {
            float4 a0 = *(const float4*)&As[kk][tm * 8];
            float4 a1 = *(const float4*)&As[kk][tm * 8 + 4];
            float4 b0 = *(const float4*)&Bs[kk][tn * 8];
            float4 b1 = *(const float4*)&Bs[kk][tn * 8 + 4];
            float a[8] = {a0.x, a0.y, a0.z, a0.w, a1.x, a1.y, a1.z, a1.w};
            float b[8] = {b0.x, b0.y, b0.z, b0.w, b1.x, b1.y, b1.z, b1.w};
#pragma unroll
            for (int i = 0; i < 8; i++)
#pragma unroll
                for (int j = 0; j < 8; j++)
                    acc[i][j] += a[i] * b[j];
        }
        __syncthreads();
    }

    float bb[8];
#pragma unroll
    for (int j = 0; j < 8; j++) bb[j] = bias[n0 + tn * 8 + j];

#pragma unroll
    for (int i = 0; i < 8; i++) {
        float* crow = C + (size_t)(row0 + tm * 8 + i) * ldc + n0 + tn * 8;
        float4 o0 = make_float4(acc[i][0] + bb[0], acc[i][1] + bb[1],
                                acc[i][2] + bb[2], acc[i][3] + bb[3]);
        float4 o1 = make_float4(acc[i][4] + bb[4], acc[i][5] + bb[5],
                                acc[i][6] + bb[6], acc[i][7] + bb[7]);
        *(float4*)(crow)     = o0;
        *(float4*)(crow + 4) = o1;
    }
}

// ---------------------------------------------------------------------------
// Attention: one block per (batch, head). 128 threads.
// q/k/v loaded to smem (64x32 each), scores 64x65 (padded), fused rpb bias,
// row softmax, AV, write to g_att[b, n, h*32+d].
// ---------------------------------------------------------------------------
__global__ __launch_bounds__(128) void attn_kernel(
    const float* __restrict__ qkv, const float* __restrict__ rpb,
    const int* __restrict__ relidx, float* __restrict__ out)
{
    const int h = blockIdx.x % NHEAD;
    const int b = blockIdx.x / NHEAD;
    const int t = threadIdx.x;

    __shared__ float qs[64][32];
    __shared__ float ks[64][32];
    __shared__ float vs[64][32];
    __shared__ float sc[64][65];   // padded to kill softmax bank conflicts

    const int n    = t >> 1;
    const int half = t & 1;

    const float* base = qkv + (size_t)(b * 64 + n) * QKVW + h * HDIM + half * 16;
#pragma unroll
    for (int i = 0; i < 4; i++) {
        *(float4*)&qs[n][half * 16 + i * 4] = *(const float4*)(base + 0   + i * 4);
        *(float4*)&ks[n][half * 16 + i * 4] = *(const float4*)(base + 192 + i * 4);
        *(float4*)&vs[n][half * 16 + i * 4] = *(const float4*)(base + 384 + i * 4);
    }
    __syncthreads();

    // Scores: thread handles row n, 32 columns (half)
    float qr[32];
#pragma unroll
    for (int i = 0; i < 32; i++) qr[i] = qs[n][i];

    const float scale = 0.1767766952966369f;   // 1/sqrt(32)
    const int mbase = half * 32;
    const int* ri = relidx + n * 64;

    for (int j = 0; j < 32; j++) {
        const int m = mbase + j;
        float a = 0.0f;
#pragma unroll
        for (int kk = 0; kk < 32; kk++) a += qr[kk] * ks[m][kk];
        sc[n][m] = a * scale + rpb[ri[m] * NHEAD + h];
    }
    __syncthreads();

    // Softmax per row (first 64 threads)
    if (t < 64) {
        float mx = -1e30f;
#pragma unroll
        for (int m = 0; m < 64; m++) mx = fmaxf(mx, sc[t][m]);
        float s = 0.0f;
#pragma unroll
        for (int m = 0; m < 64; m++) {
            float e = __expf(sc[t][m] - mx);
            s += e;
            sc[t][m] = e;
        }
        float inv = 1.0f / s;
#pragma unroll
        for (int m = 0; m < 64; m++) sc[t][m] *= inv;
    }
    __syncthreads();

    // AV: thread handles row n, 16 d-columns (half)
    const int dbase = half * 16;
    float acc[16];
#pragma unroll
    for (int d = 0; d < 16; d++) acc[d] = 0.0f;

    for (int m = 0; m < 64; m++) {
        const float s = sc[n][m];
#pragma unroll
        for (int d = 0; d < 16; d++) acc[d] += s * vs[m][dbase + d];
    }

    float* op = out + (size_t)(b * 64 + n) * CDIM + h * HDIM + dbase;
#pragma unroll
    for (int i = 0; i < 4; i++)
        *(float4*)(op + i * 4) = make_float4(acc[i * 4 + 0], acc[i * 4 + 1],
                                             acc[i * 4 + 2], acc[i * 4 + 3]);
}

// ---------------------------------------------------------------------------
// Positional conv branch: one block per batch window, 256 threads.
// v_r (from qkv cols 576..767) -> depthwise 5x5 SAME -> grouped 1x1 (NH groups)
// -> accumulate into g_att.  Dynamic smem: vt[64][192] + pt[64][192] = 96 KB.
// ---------------------------------------------------------------------------
__global__ __launch_bounds__(256) void conv_kernel(
    const float* __restrict__ qkv, const float* __restrict__ dw_w,
    const float* __restrict__ dw_b, const float* __restrict__ pw_w,
    const float* __restrict__ pw_b, float* __restrict__ att)
{
    extern __shared__ float sm[];
    float* vt = sm;                  // [pixel][channel] = [64][192]
    float* pt = sm + 64 * 192;       // depthwise output, same layout

    const int b = blockIdx.x;
    const int t = threadIdx.x;

    const float* src = qkv + (size_t)b * 64 * QKVW + 576;
#pragma unroll
    for (int it = 0; it < 48; it++) {
        const int idx = t + it * 256;        // = p*192 + c
        const int p = idx / 192;
        const int c = idx - p * 192;
        vt[idx] = src[(size_t)p * QKVW + c];
    }
    __syncthreads();

    // Depthwise 5x5, SAME padding over 8x8
#pragma unroll
    for (int it = 0; it < 48; it++) {
        const int idx = t + it * 256;
        const int p = idx / 192;
        const int c = idx - p * 192;
        const int y = p >> 3, x = p & 7;
        float a = dw_b[c];
        const float* w = dw_w + c * 25;
#pragma unroll
        for (int ky = 0; ky < 5; ky++) {
            const int yy = y + ky - 2;
            if (yy < 0 || yy > 7) continue;
#pragma unroll
            for (int kx = 0; kx < 5; kx++) {
                const int xx = x + kx - 2;
                if (xx < 0 || xx > 7) continue;
                a += vt[(yy * 8 + xx) * 192 + c] * w[ky * 5 + kx];
            }
        }
        pt[idx] = a;
    }
    __syncthreads();

    // Grouped 1x1 (6 groups of 32), accumulate into attention output
    float* dst = att + (size_t)b * 64 * CDIM;
#pragma unroll
    for (int it = 0; it < 48; it++) {
        const int idx = t + it * 256;
        const int p = idx / 192;
        const int c = idx - p * 192;
        const float* pw  = pw_w + c * 32;
        const float* pin = pt + p * 192 + (c >> 5) * 32;
        float a = pw_b[c];
#pragma unroll
        for (int d = 0; d < 32; d++) a += pin[d] * pw[d];
        dst[idx] += a;
    }
}

// ---------------------------------------------------------------------------
extern "C" void kernel_launch(void* const* d_in, const int* in_sizes, int n_in,
                              void* d_out, int out_size)
{
    const float* x      = (const float*)d_in[0];
    const float* wq     = (const float*)d_in[1];
    const float* bq     = (const float*)d_in[2];
    const float* wkv    = (const float*)d_in[3];
    const float* bkv    = (const float*)d_in[4];
    const float* rpb    = (const float*)d_in[5];
    const int*   relidx = (const int*)  d_in[6];
    const float* dw_w   = (const float*)d_in[7];
    const float* dw_b   = (const float*)d_in[8];
    const float* pw_w   = (const float*)d_in[9];
    const float* pw_b   = (const float*)d_in[10];
    const float* proj_w = (const float*)d_in[11];
    const float* proj_b = (const float*)d_in[12];
    float* out = (float*)d_out;

    float* qkv = nullptr;
    float* att = nullptr;
    cudaGetSymbolAddress((void**)&qkv, g_qkv);
    cudaGetSymbolAddress((void**)&att, g_att);

    const dim3 blk(128);

    // 1) q = x @ wq + bq  -> qkv[:, 0:192]
    gemm_bias_kernel<<<dim3(MROWS / 128, 192 / 64), blk>>>(x, wq, bq, qkv, CDIM, 192, QKVW);
    // 2) kv = x @ wkv + bkv -> qkv[:, 192:768]
    gemm_bias_kernel<<<dim3(MROWS / 128, 576 / 64), blk>>>(x, wkv, bkv, qkv + 192, CDIM, 576, QKVW);
    // 3) attention -> g_att
    attn_kernel<<<BATCH * NHEAD, 128>>>(qkv, rpb, relidx, att);
    // 4) conv branch accumulates into g_att
    cudaFuncSetAttribute(conv_kernel, cudaFuncAttributeMaxDynamicSharedMemorySize, 98304);
    conv_kernel<<<BATCH, 256, 98304>>>(qkv, dw_w, dw_b, pw_w, pw_b, att);
    // 5) out = g_att @ proj_w + proj_b
    gemm_bias_kernel<<<dim3(MROWS / 128, 192 / 64), blk>>>(att, proj_w, proj_b, out, CDIM, 192, CDIM);
}

// round 5
// speedup vs baseline: 1.1066x; 1.1066x over previous
#include <cuda_runtime.h>
#include <cuda_bf16.h>
#include <cstdint>
#include <cstddef>

// Problem constants
#define BATCH 4096
#define NTOK 64
#define CDIM 192
#define NHEAD 6
#define HDIM 32
#define MROWS (BATCH * NTOK)   // 262144
#define QKVW 768               // q(192) + k(192) + v(192) + v_r(192)
#define KDIM 192

// ---------------------------------------------------------------------------
// Device scratch (no allocations allowed)
// ---------------------------------------------------------------------------
__device__ float g_qkv[(size_t)MROWS * QKVW];          // 805 MB
__device__ float g_att[(size_t)MROWS * CDIM];          // 201 MB
__device__ __nv_bfloat16 g_ah[(size_t)MROWS * KDIM];   // 100 MB (x hi)
__device__ __nv_bfloat16 g_al[(size_t)MROWS * KDIM];   // 100 MB (x lo)
__device__ __nv_bfloat16 g_ath[(size_t)MROWS * KDIM];  // att hi
__device__ __nv_bfloat16 g_atl[(size_t)MROWS * KDIM];  // att lo
__device__ __nv_bfloat16 g_wh[768 * 192];              // qkv weights (N-major) hi
__device__ __nv_bfloat16 g_wl[768 * 192];
__device__ __nv_bfloat16 g_pwh[192 * 192];             // proj weights (N-major) hi
__device__ __nv_bfloat16 g_pwl[192 * 192];
__device__ float g_bias[768];                          // concat(bq, bkv)

// ---------------------------------------------------------------------------
// MMA helpers (portable on compute_103: ldmatrix + mma.sync are sm_80 features)
// ---------------------------------------------------------------------------
__device__ __forceinline__ uint32_t smem_u32(const void* p) {
    uint32_t a;
    asm("{ .reg .u64 t; cvta.to.shared.u64 t, %1; cvt.u32.u64 %0, t; }"
        : "=r"(a) : "l"(p));
    return a;
}

__device__ __forceinline__ void ldsm4(uint32_t addr, uint32_t r[4]) {
    asm volatile("ldmatrix.sync.aligned.m8n8.x4.shared.b16 {%0,%1,%2,%3}, [%4];"
        : "=r"(r[0]), "=r"(r[1]), "=r"(r[2]), "=r"(r[3]) : "r"(addr));
}

__device__ __forceinline__ void mma16816(float c[4], const uint32_t a[4],
                                         uint32_t b0, uint32_t b1) {
    asm volatile(
        "mma.sync.aligned.m16n8k16.row.col.f32.bf16.bf16.f32 "
        "{%0,%1,%2,%3}, {%4,%5,%6,%7}, {%8,%9}, {%0,%1,%2,%3};"
        : "+f"(c[0]), "+f"(c[1]), "+f"(c[2]), "+f"(c[3])
        : "r"(a[0]), "r"(a[1]), "r"(a[2]), "r"(a[3]), "r"(b0), "r"(b1));
}

// ---------------------------------------------------------------------------
// fp32 -> (bf16 hi, bf16 lo) split
// ---------------------------------------------------------------------------
__device__ __forceinline__ void bf16_split(float v, __nv_bfloat16& h, __nv_bfloat16& l) {
    h = __float2bfloat16(v);
    l = __float2bfloat16(v - __bfloat162float(h));
}

__global__ __launch_bounds__(256) void split_kernel(
    const float* __restrict__ in, __nv_bfloat16* __restrict__ hi,
    __nv_bfloat16* __restrict__ lo, int n4)
{
    int i = blockIdx.x * 256 + threadIdx.x;
    if (i >= n4) return;
    float4 v = ((const float4*)in)[i];
    __nv_bfloat16 h[4], l[4];
    bf16_split(v.x, h[0], l[0]);
    bf16_split(v.y, h[1], l[1]);
    bf16_split(v.z, h[2], l[2]);
    bf16_split(v.w, h[3], l[3]);
    ((uint64_t*)hi)[i] = *(const uint64_t*)h;
    ((uint64_t*)lo)[i] = *(const uint64_t*)l;
}

// Weights: transpose to N-major [n][k] and split; concat biases.
__global__ __launch_bounds__(256) void prep_w_kernel(
    const float* __restrict__ wq, const float* __restrict__ wkv,
    const float* __restrict__ bq, const float* __restrict__ bkv,
    const float* __restrict__ projw)
{
    int idx = blockIdx.x * 256 + threadIdx.x;
    if (idx < 768 * 192) {
        int n = idx / 192, k = idx % 192;
        float v = (n < 192) ? wq[k * 192 + n] : wkv[k * 576 + (n - 192)];
        bf16_split(v, g_wh[idx], g_wl[idx]);
    } else if (idx < 768 * 192 + 192 * 192) {
        int j = idx - 768 * 192;
        int n = j / 192, k = j % 192;
        bf16_split(projw[k * 192 + n], g_pwh[j], g_pwl[j]);
    }
    if (idx < 768) g_bias[idx] = (idx < 192) ? bq[idx] : bkv[idx - 192];
}

// ---------------------------------------------------------------------------
// HMMA GEMM: C[64x64 tile] = (Ah+Al)[64xK] @ (Bh+Bl)^T[Kx64] + bias
// 3-term split: Ah*Bh + Al*Bh + Ah*Bl, fp32 accum. K=192 resident in SMEM.
// 128 threads = 4 warps (2x2 grid of 32x32 warp tiles). Padded rows (+8 bf16)
// give conflict-free ldmatrix. grid = (Ntiles, Mtiles).
// ---------------------------------------------------------------------------
#define LDS 200                        // row stride in bf16 elems (192 + 8 pad)
#define SM_AH 0
#define SM_AL (64 * LDS)
#define SM_BH (128 * LDS)
#define SM_BL (192 * LDS)
#define GEMM_SMEM (256 * LDS * 2)      // 102400 bytes -> 2 CTAs/SM

__global__ __launch_bounds__(128) void gemm_tc_kernel(
    const __nv_bfloat16* __restrict__ Ah, const __nv_bfloat16* __restrict__ Al,
    const __nv_bfloat16* __restrict__ Bh, const __nv_bfloat16* __restrict__ Bl,
    const float* __restrict__ bias, float* __restrict__ C, int ldc)
{
    extern __shared__ __nv_bfloat16 sm[];
    const int t = threadIdx.x;
    const int lane = t & 31;
    const int wid = t >> 5;
    const int wm = wid >> 1;          // 0..1
    const int wn = wid & 1;           // 0..1
    const int n0   = blockIdx.x * 64;
    const int row0 = blockIdx.y * 64;

    // Load A tile (64x192, hi+lo): 8B vector per iter
#pragma unroll
    for (int it = 0; it < 24; it++) {
        int idx = it * 128 + t;            // 0..3071
        int r = idx / 48;
        int k = (idx % 48) * 4;
        size_t g = (size_t)(row0 + r) * KDIM + k;
        int s = r * LDS + k;
        *(uint64_t*)(sm + SM_AH + s) = *(const uint64_t*)(Ah + g);
        *(uint64_t*)(sm + SM_AL + s) = *(const uint64_t*)(Al + g);
    }
    // Load B tile (64 n-rows x 192, hi+lo)
#pragma unroll
    for (int it = 0; it < 24; it++) {
        int idx = it * 128 + t;
        int r = idx / 48;
        int k = (idx % 48) * 4;
        size_t g = (size_t)(n0 + r) * KDIM + k;
        int s = r * LDS + k;
        *(uint64_t*)(sm + SM_BH + s) = *(const uint64_t*)(Bh + g);
        *(uint64_t*)(sm + SM_BL + s) = *(const uint64_t*)(Bl + g);
    }
    __syncthreads();

    float acc[2][4][4];
#pragma unroll
    for (int i = 0; i < 2; i++)
#pragma unroll
        for (int j = 0; j < 4; j++)
#pragma unroll
            for (int e = 0; e < 4; e++) acc[i][j][e] = 0.0f;

    const uint32_t sbase = smem_u32(sm);
    // ldmatrix per-lane offsets (in elems), A: x4 covers m16 x k16
    const uint32_t aoff = (uint32_t)((wm * 32 + (lane & 15)) * LDS + ((lane >> 4) << 3));
    // B: x4 covers n16 x k16 (plain ldmatrix on [n][k] = col-major B fragment)
    const uint32_t boff = (uint32_t)((wn * 32 + (lane & 7) + ((lane >> 4) << 3)) * LDS
                                     + (((lane >> 3) & 1) << 3));

#pragma unroll
    for (int pass = 0; pass < 3; pass++) {
        const uint32_t aBase = sbase + 2u * (pass == 1 ? SM_AL : SM_AH);
        const uint32_t bBase = sbase + 2u * (pass == 2 ? SM_BL : SM_BH);
#pragma unroll
        for (int ks = 0; ks < 12; ks++) {
            const uint32_t k0 = ks * 16;
            uint32_t a0[4], a1[4], b0[4], b1[4];
            ldsm4(aBase + (aoff + k0) * 2, a0);
            ldsm4(aBase + (aoff + 16 * LDS + k0) * 2, a1);
            ldsm4(bBase + (boff + k0) * 2, b0);
            ldsm4(bBase + (boff + 16 * LDS + k0) * 2, b1);

            mma16816(acc[0][0], a0, b0[0], b0[1]);
            mma16816(acc[0][1], a0, b0[2], b0[3]);
            mma16816(acc[0][2], a0, b1[0], b1[1]);
            mma16816(acc[0][3], a0, b1[2], b1[3]);
            mma16816(acc[1][0], a1, b0[0], b0[1]);
            mma16816(acc[1][1], a1, b0[2], b0[3]);
            mma16816(acc[1][2], a1, b1[0], b1[1]);
            mma16816(acc[1][3], a1, b1[2], b1[3]);
        }
    }

    // Epilogue: direct stores with fused bias.
    // D frag: d0,d1 -> (row=lane/4, col=2*(lane%4)+{0,1}); d2,d3 -> row+8.
    const int r_base = row0 + wm * 32 + (lane >> 2);
    const int c_base = n0 + wn * 32 + (lane & 3) * 2;
#pragma unroll
    for (int nt = 0; nt < 4; nt++) {
        const int col = c_base + nt * 8;
        const float bv0 = bias[col];
        const float bv1 = bias[col + 1];
#pragma unroll
        for (int mt = 0; mt < 2; mt++) {
            const int r = r_base + mt * 16;
            float2 v0 = make_float2(acc[mt][nt][0] + bv0, acc[mt][nt][1] + bv1);
            float2 v1 = make_float2(acc[mt][nt][2] + bv0, acc[mt][nt][3] + bv1);
            *(float2*)(C + (size_t)r * ldc + col)       = v0;
            *(float2*)(C + (size_t)(r + 8) * ldc + col) = v1;
        }
    }
}

// ---------------------------------------------------------------------------
// Attention: one block per (batch, head). 128 threads. (validated in R3)
// ---------------------------------------------------------------------------
__global__ __launch_bounds__(128) void attn_kernel(
    const float* __restrict__ qkv, const float* __restrict__ rpb,
    const int* __restrict__ relidx, float* __restrict__ out)
{
    const int h = blockIdx.x % NHEAD;
    const int b = blockIdx.x / NHEAD;
    const int t = threadIdx.x;

    __shared__ float qs[64][32];
    __shared__ float ks[64][32];
    __shared__ float vs[64][32];
    __shared__ float sc[64][65];

    const int n    = t >> 1;
    const int half = t & 1;

    const float* base = qkv + (size_t)(b * 64 + n) * QKVW + h * HDIM + half * 16;
#pragma unroll
    for (int i = 0; i < 4; i++) {
        *(float4*)&qs[n][half * 16 + i * 4] = *(const float4*)(base + 0   + i * 4);
        *(float4*)&ks[n][half * 16 + i * 4] = *(const float4*)(base + 192 + i * 4);
        *(float4*)&vs[n][half * 16 + i * 4] = *(const float4*)(base + 384 + i * 4);
    }
    __syncthreads();

    float qr[32];
#pragma unroll
    for (int i = 0; i < 32; i++) qr[i] = qs[n][i];

    const float scale = 0.1767766952966369f;
    const int mbase = half * 32;
    const int* ri = relidx + n * 64;

    for (int j = 0; j < 32; j++) {
        const int m = mbase + j;
        float a = 0.0f;
#pragma unroll
        for (int kk = 0; kk < 32; kk++) a += qr[kk] * ks[m][kk];
        sc[n][m] = a * scale + rpb[ri[m] * NHEAD + h];
    }
    __syncthreads();

    if (t < 64) {
        float mx = -1e30f;
#pragma unroll
        for (int m = 0; m < 64; m++) mx = fmaxf(mx, sc[t][m]);
        float s = 0.0f;
#pragma unroll
        for (int m = 0; m < 64; m++) {
            float e = __expf(sc[t][m] - mx);
            s += e;
            sc[t][m] = e;
        }
        float inv = 1.0f / s;
#pragma unroll
        for (int m = 0; m < 64; m++) sc[t][m] *= inv;
    }
    __syncthreads();

    const int dbase = half * 16;
    float acc[16];
#pragma unroll
    for (int d = 0; d < 16; d++) acc[d] = 0.0f;

    for (int m = 0; m < 64; m++) {
        const float s = sc[n][m];
#pragma unroll
        for (int d = 0; d < 16; d++) acc[d] += s * vs[m][dbase + d];
    }

    float* op = out + (size_t)(b * 64 + n) * CDIM + h * HDIM + dbase;
#pragma unroll
    for (int i = 0; i < 4; i++)
        *(float4*)(op + i * 4) = make_float4(acc[i * 4 + 0], acc[i * 4 + 1],
                                             acc[i * 4 + 2], acc[i * 4 + 3]);
}

// ---------------------------------------------------------------------------
// Positional conv branch (validated in R3)
// ---------------------------------------------------------------------------
__global__ __launch_bounds__(256) void conv_kernel(
    const float* __restrict__ qkv, const float* __restrict__ dw_w,
    const float* __restrict__ dw_b, const float* __restrict__ pw_w,
    const float* __restrict__ pw_b, float* __restrict__ att)
{
    extern __shared__ float smf[];
    float* vt = smf;
    float* pt = smf + 64 * 192;

    const int b = blockIdx.x;
    const int t = threadIdx.x;

    const float* src = qkv + (size_t)b * 64 * QKVW + 576;
#pragma unroll
    for (int it = 0; it < 48; it++) {
        const int idx = t + it * 256;
        const int p = idx / 192;
        const int c = idx - p * 192;
        vt[idx] = src[(size_t)p * QKVW + c];
    }
    __syncthreads();

#pragma unroll
    for (int it = 0; it < 48; it++) {
        const int idx = t + it * 256;
        const int p = idx / 192;
        const int c = idx - p * 192;
        const int y = p >> 3, x = p & 7;
        float a = dw_b[c];
        const float* w = dw_w + c * 25;
#pragma unroll
        for (int ky = 0; ky < 5; ky++) {
            const int yy = y + ky - 2;
            if (yy < 0 || yy > 7) continue;
#pragma unroll
            for (int kx = 0; kx < 5; kx++) {
                const int xx = x + kx - 2;
                if (xx < 0 || xx > 7) continue;
                a += vt[(yy * 8 + xx) * 192 + c] * w[ky * 5 + kx];
            }
        }
        pt[idx] = a;
    }
    __syncthreads();

    float* dst = att + (size_t)b * 64 * CDIM;
#pragma unroll
    for (int it = 0; it < 48; it++) {
        const int idx = t + it * 256;
        const int p = idx / 192;
        const int c = idx - p * 192;
        const float* pw  = pw_w + c * 32;
        const float* pin = pt + p * 192 + (c >> 5) * 32;
        float a = pw_b[c];
#pragma unroll
        for (int d = 0; d < 32; d++) a += pin[d] * pw[d];
        dst[idx] += a;
    }
}

// ---------------------------------------------------------------------------
extern "C" void kernel_launch(void* const* d_in, const int* in_sizes, int n_in,
                              void* d_out, int out_size)
{
    const float* x      = (const float*)d_in[0];
    const float* wq     = (const float*)d_in[1];
    const float* bq     = (const float*)d_in[2];
    const float* wkv    = (const float*)d_in[3];
    const float* bkv    = (const float*)d_in[4];
    const float* rpb    = (const float*)d_in[5];
    const int*   relidx = (const int*)  d_in[6];
    const float* dw_w   = (const float*)d_in[7];
    const float* dw_b   = (const float*)d_in[8];
    const float* pw_w   = (const float*)d_in[9];
    const float* pw_b   = (const float*)d_in[10];
    const float* proj_w = (const float*)d_in[11];
    const float* proj_b = (const float*)d_in[12];
    float* out = (float*)d_out;

    float *qkv, *att, *biasc;
    __nv_bfloat16 *ah, *al, *ath, *atl, *wh, *wl, *pwh, *pwl;
    cudaGetSymbolAddress((void**)&qkv,  g_qkv);
    cudaGetSymbolAddress((void**)&att,  g_att);
    cudaGetSymbolAddress((void**)&ah,   g_ah);
    cudaGetSymbolAddress((void**)&al,   g_al);
    cudaGetSymbolAddress((void**)&ath,  g_ath);
    cudaGetSymbolAddress((void**)&atl,  g_atl);
    cudaGetSymbolAddress((void**)&wh,   g_wh);
    cudaGetSymbolAddress((void**)&wl,   g_wl);
    cudaGetSymbolAddress((void**)&pwh,  g_pwh);
    cudaGetSymbolAddress((void**)&pwl,  g_pwl);
    cudaGetSymbolAddress((void**)&biasc, g_bias);

    cudaFuncSetAttribute(gemm_tc_kernel,
                         cudaFuncAttributeMaxDynamicSharedMemorySize, GEMM_SMEM);
    cudaFuncSetAttribute(conv_kernel,
                         cudaFuncAttributeMaxDynamicSharedMemorySize, 98304);

    const int n4 = MROWS * KDIM / 4;

    // 0) weight prep + input split
    prep_w_kernel<<<(768 * 192 + 192 * 192 + 255) / 256, 256>>>(wq, wkv, bq, bkv, proj_w);
    split_kernel<<<(n4 + 255) / 256, 256>>>(x, ah, al, n4);

    // 1) fused q|k|v|v_r GEMM: [262144 x 192] @ [192 x 768] -> g_qkv
    gemm_tc_kernel<<<dim3(QKVW / 64, MROWS / 64), 128, GEMM_SMEM>>>(
        ah, al, wh, wl, biasc, qkv, QKVW);

    // 2) attention -> g_att
    attn_kernel<<<BATCH * NHEAD, 128>>>(qkv, rpb, relidx, att);

    // 3) conv branch accumulates into g_att
    conv_kernel<<<BATCH, 256, 98304>>>(qkv, dw_w, dw_b, pw_w, pw_b, att);

    // 4) split attention output, then proj GEMM -> d_out
    split_kernel<<<(n4 + 255) / 256, 256>>>(att, ath, atl, n4);
    gemm_tc_kernel<<<dim3(CDIM / 64, MROWS / 64), 128, GEMM_SMEM>>>(
        ath, atl, pwh, pwl, proj_b, out, CDIM);
}

// round 6
// speedup vs baseline: 3.1434x; 2.8406x over previous
#include <cuda_runtime.h>
#include <cuda_bf16.h>
#include <cstdint>
#include <cstddef>

// Problem constants
#define BATCH 4096
#define NTOK 64
#define CDIM 192
#define NHEAD 6
#define HDIM 32
#define MROWS (BATCH * NTOK)   // 262144
#define QKVW 768               // q(192) + k(192) + v(192) + v_r(192)
#define KDIM 192

// ---------------------------------------------------------------------------
// Device scratch (no allocations allowed)
// ---------------------------------------------------------------------------
__device__ float g_qkv[(size_t)MROWS * QKVW];          // 805 MB
__device__ float g_att[(size_t)MROWS * CDIM];          // 201 MB
__device__ __nv_bfloat16 g_ah[(size_t)MROWS * KDIM];
__device__ __nv_bfloat16 g_al[(size_t)MROWS * KDIM];
__device__ __nv_bfloat16 g_ath[(size_t)MROWS * KDIM];
__device__ __nv_bfloat16 g_atl[(size_t)MROWS * KDIM];
__device__ __nv_bfloat16 g_wh[768 * 192];              // qkv weights (N-major) hi
__device__ __nv_bfloat16 g_wl[768 * 192];
__device__ __nv_bfloat16 g_pwh[192 * 192];
__device__ __nv_bfloat16 g_pwl[192 * 192];
__device__ float g_bias[768];                          // concat(bq, bkv)
__device__ float g_bmat[NHEAD * NTOK * NTOK];          // precomputed rel-pos bias

// ---------------------------------------------------------------------------
// MMA helpers (portable on compute_103: ldmatrix + mma.sync are sm_80 features)
// ---------------------------------------------------------------------------
__device__ __forceinline__ uint32_t smem_u32(const void* p) {
    uint32_t a;
    asm("{ .reg .u64 t; cvta.to.shared.u64 t, %1; cvt.u32.u64 %0, t; }"
        : "=r"(a) : "l"(p));
    return a;
}

__device__ __forceinline__ void ldsm4(uint32_t addr, uint32_t r[4]) {
    asm volatile("ldmatrix.sync.aligned.m8n8.x4.shared.b16 {%0,%1,%2,%3}, [%4];"
        : "=r"(r[0]), "=r"(r[1]), "=r"(r[2]), "=r"(r[3]) : "r"(addr));
}

__device__ __forceinline__ void mma16816(float c[4], const uint32_t a[4],
                                         uint32_t b0, uint32_t b1) {
    asm volatile(
        "mma.sync.aligned.m16n8k16.row.col.f32.bf16.bf16.f32 "
        "{%0,%1,%2,%3}, {%4,%5,%6,%7}, {%8,%9}, {%0,%1,%2,%3};"
        : "+f"(c[0]), "+f"(c[1]), "+f"(c[2]), "+f"(c[3])
        : "r"(a[0]), "r"(a[1]), "r"(a[2]), "r"(a[3]), "r"(b0), "r"(b1));
}

// ---------------------------------------------------------------------------
// fp32 -> (bf16 hi, bf16 lo) split
// ---------------------------------------------------------------------------
__device__ __forceinline__ void bf16_split(float v, __nv_bfloat16& h, __nv_bfloat16& l) {
    h = __float2bfloat16(v);
    l = __float2bfloat16(v - __bfloat162float(h));
}

__global__ __launch_bounds__(256) void split_kernel(
    const float* __restrict__ in, __nv_bfloat16* __restrict__ hi,
    __nv_bfloat16* __restrict__ lo, int n4)
{
    int i = blockIdx.x * 256 + threadIdx.x;
    if (i >= n4) return;
    float4 v = ((const float4*)in)[i];
    __nv_bfloat16 h[4], l[4];
    bf16_split(v.x, h[0], l[0]);
    bf16_split(v.y, h[1], l[1]);
    bf16_split(v.z, h[2], l[2]);
    bf16_split(v.w, h[3], l[3]);
    ((uint64_t*)hi)[i] = *(const uint64_t*)h;
    ((uint64_t*)lo)[i] = *(const uint64_t*)l;
}

// Weights: transpose to N-major [n][k] and split; concat biases; bias matrices.
__global__ __launch_bounds__(256) void prep_w_kernel(
    const float* __restrict__ wq, const float* __restrict__ wkv,
    const float* __restrict__ bq, const float* __restrict__ bkv,
    const float* __restrict__ projw,
    const float* __restrict__ rpb, const int* __restrict__ relidx)
{
    int idx = blockIdx.x * 256 + threadIdx.x;
    if (idx < 768 * 192) {
        int n = idx / 192, k = idx % 192;
        float v = (n < 192) ? wq[k * 192 + n] : wkv[k * 576 + (n - 192)];
        bf16_split(v, g_wh[idx], g_wl[idx]);
    } else if (idx < 768 * 192 + 192 * 192) {
        int j = idx - 768 * 192;
        int n = j / 192, k = j % 192;
        bf16_split(projw[k * 192 + n], g_pwh[j], g_pwl[j]);
    }
    if (idx < 768) g_bias[idx] = (idx < 192) ? bq[idx] : bkv[idx - 192];
    if (idx < NTOK * NTOK) {
        int ri = relidx[idx];
#pragma unroll
        for (int h = 0; h < NHEAD; h++)
            g_bmat[h * (NTOK * NTOK) + idx] = rpb[ri * NHEAD + h];
    }
}

// ---------------------------------------------------------------------------
// HMMA GEMM: C[64x64 tile] = (Ah+Al)[64xK] @ (Bh+Bl)^T[Kx64] + bias
// (validated in R5, unchanged)
// ---------------------------------------------------------------------------
#define LDS 200
#define SM_AH 0
#define SM_AL (64 * LDS)
#define SM_BH (128 * LDS)
#define SM_BL (192 * LDS)
#define GEMM_SMEM (256 * LDS * 2)      // 102400 bytes

__global__ __launch_bounds__(128) void gemm_tc_kernel(
    const __nv_bfloat16* __restrict__ Ah, const __nv_bfloat16* __restrict__ Al,
    const __nv_bfloat16* __restrict__ Bh, const __nv_bfloat16* __restrict__ Bl,
    const float* __restrict__ bias, float* __restrict__ C, int ldc)
{
    extern __shared__ __nv_bfloat16 sm[];
    const int t = threadIdx.x;
    const int lane = t & 31;
    const int wid = t >> 5;
    const int wm = wid >> 1;
    const int wn = wid & 1;
    const int n0   = blockIdx.x * 64;
    const int row0 = blockIdx.y * 64;

#pragma unroll
    for (int it = 0; it < 24; it++) {
        int idx = it * 128 + t;
        int r = idx / 48;
        int k = (idx % 48) * 4;
        size_t g = (size_t)(row0 + r) * KDIM + k;
        int s = r * LDS + k;
        *(uint64_t*)(sm + SM_AH + s) = *(const uint64_t*)(Ah + g);
        *(uint64_t*)(sm + SM_AL + s) = *(const uint64_t*)(Al + g);
    }
#pragma unroll
    for (int it = 0; it < 24; it++) {
        int idx = it * 128 + t;
        int r = idx / 48;
        int k = (idx % 48) * 4;
        size_t g = (size_t)(n0 + r) * KDIM + k;
        int s = r * LDS + k;
        *(uint64_t*)(sm + SM_BH + s) = *(const uint64_t*)(Bh + g);
        *(uint64_t*)(sm + SM_BL + s) = *(const uint64_t*)(Bl + g);
    }
    __syncthreads();

    float acc[2][4][4];
#pragma unroll
    for (int i = 0; i < 2; i++)
#pragma unroll
        for (int j = 0; j < 4; j++)
#pragma unroll
            for (int e = 0; e < 4; e++) acc[i][j][e] = 0.0f;

    const uint32_t sbase = smem_u32(sm);
    const uint32_t aoff = (uint32_t)((wm * 32 + (lane & 15)) * LDS + ((lane >> 4) << 3));
    const uint32_t boff = (uint32_t)((wn * 32 + (lane & 7) + ((lane >> 4) << 3)) * LDS
                                     + (((lane >> 3) & 1) << 3));

#pragma unroll
    for (int pass = 0; pass < 3; pass++) {
        const uint32_t aBase = sbase + 2u * (pass == 1 ? SM_AL : SM_AH);
        const uint32_t bBase = sbase + 2u * (pass == 2 ? SM_BL : SM_BH);
#pragma unroll
        for (int ks = 0; ks < 12; ks++) {
            const uint32_t k0 = ks * 16;
            uint32_t a0[4], a1[4], b0[4], b1[4];
            ldsm4(aBase + (aoff + k0) * 2, a0);
            ldsm4(aBase + (aoff + 16 * LDS + k0) * 2, a1);
            ldsm4(bBase + (boff + k0) * 2, b0);
            ldsm4(bBase + (boff + 16 * LDS + k0) * 2, b1);

            mma16816(acc[0][0], a0, b0[0], b0[1]);
            mma16816(acc[0][1], a0, b0[2], b0[3]);
            mma16816(acc[0][2], a0, b1[0], b1[1]);
            mma16816(acc[0][3], a0, b1[2], b1[3]);
            mma16816(acc[1][0], a1, b0[0], b0[1]);
            mma16816(acc[1][1], a1, b0[2], b0[3]);
            mma16816(acc[1][2], a1, b1[0], b1[1]);
            mma16816(acc[1][3], a1, b1[2], b1[3]);
        }
    }

    const int r_base = row0 + wm * 32 + (lane >> 2);
    const int c_base = n0 + wn * 32 + (lane & 3) * 2;
#pragma unroll
    for (int nt = 0; nt < 4; nt++) {
        const int col = c_base + nt * 8;
        const float bv0 = bias[col];
        const float bv1 = bias[col + 1];
#pragma unroll
        for (int mt = 0; mt < 2; mt++) {
            const int r = r_base + mt * 16;
            float2 v0 = make_float2(acc[mt][nt][0] + bv0, acc[mt][nt][1] + bv1);
            float2 v1 = make_float2(acc[mt][nt][2] + bv0, acc[mt][nt][3] + bv1);
            *(float2*)(C + (size_t)r * ldc + col)       = v0;
            *(float2*)(C + (size_t)(r + 8) * ldc + col) = v1;
        }
    }
}

// ---------------------------------------------------------------------------
// Attention: one block per (batch, head). 128 threads.
// R5 structure + precomputed bias (no gathers), scale folded into q,
// 2-way ILP in scores, fully-parallel pair-reduced softmax.
// ---------------------------------------------------------------------------
__global__ __launch_bounds__(128) void attn_kernel(
    const float* __restrict__ qkv, const float* __restrict__ bmat,
    float* __restrict__ out)
{
    const int h = blockIdx.x % NHEAD;
    const int b = blockIdx.x / NHEAD;
    const int t = threadIdx.x;

    __shared__ float qs[64][32];
    __shared__ float ks[64][32];
    __shared__ float vs[64][32];
    __shared__ float sc[64][65];

    const int n    = t >> 1;
    const int half = t & 1;
    const float scale = 0.1767766952966369f;   // 1/sqrt(32)

    const float* base = qkv + (size_t)(b * 64 + n) * QKVW + h * HDIM + half * 16;
#pragma unroll
    for (int i = 0; i < 4; i++) {
        float4 qv = *(const float4*)(base + 0 + i * 4);
        qv.x *= scale; qv.y *= scale; qv.z *= scale; qv.w *= scale;
        *(float4*)&qs[n][half * 16 + i * 4] = qv;
        *(float4*)&ks[n][half * 16 + i * 4] = *(const float4*)(base + 192 + i * 4);
        *(float4*)&vs[n][half * 16 + i * 4] = *(const float4*)(base + 384 + i * 4);
    }
    __syncthreads();

    float qr[32];
#pragma unroll
    for (int i = 0; i < 32; i++) qr[i] = qs[n][i];

    const int mbase = half * 32;
    const float* bm = bmat + h * 4096 + n * 64;

    // Scores: 2 columns per iteration, independent accumulator chains
#pragma unroll
    for (int j = 0; j < 32; j += 2) {
        const int m0 = mbase + j;
        const int m1 = m0 + 1;
        float a0 = 0.0f, a1 = 0.0f;
#pragma unroll
        for (int kk = 0; kk < 32; kk++) {
            const float q = qr[kk];
            a0 += q * ks[m0][kk];
            a1 += q * ks[m1][kk];
        }
        sc[n][m0] = a0 + bm[m0];
        sc[n][m1] = a1 + bm[m1];
    }
    __syncthreads();

    // Softmax: each thread owns half a row; pair-combine via shfl_xor(1)
    {
        float mx = -1e30f;
#pragma unroll
        for (int i = 0; i < 32; i++) mx = fmaxf(mx, sc[n][mbase + i]);
        mx = fmaxf(mx, __shfl_xor_sync(0xffffffffu, mx, 1));
        float s = 0.0f;
#pragma unroll
        for (int i = 0; i < 32; i++) {
            float e = __expf(sc[n][mbase + i] - mx);
            s += e;
            sc[n][mbase + i] = e;
        }
        s += __shfl_xor_sync(0xffffffffu, s, 1);
        const float inv = 1.0f / s;
#pragma unroll
        for (int i = 0; i < 32; i++) sc[n][mbase + i] *= inv;
    }
    __syncthreads();

    // AV: thread handles row n, 16 d-columns
    const int dbase = half * 16;
    float acc[16];
#pragma unroll
    for (int d = 0; d < 16; d++) acc[d] = 0.0f;

    for (int m = 0; m < 64; m++) {
        const float s = sc[n][m];
#pragma unroll
        for (int d = 0; d < 16; d++) acc[d] += s * vs[m][dbase + d];
    }

    float* op = out + (size_t)(b * 64 + n) * CDIM + h * HDIM + dbase;
#pragma unroll
    for (int i = 0; i < 4; i++)
        *(float4*)(op + i * 4) = make_float4(acc[i * 4 + 0], acc[i * 4 + 1],
                                             acc[i * 4 + 2], acc[i * 4 + 3]);
}

// ---------------------------------------------------------------------------
// Positional conv branch, rewritten: 192 threads, one per channel.
// Depthwise 5x5 entirely in registers (static unroll -> static guards),
// pw_w staged transposed in padded smem, 1x1 via broadcast LDS.128.
// Dynamic smem: vt 48KB + pt 48KB + pw_s 24.1KB = 123008 B.
// ---------------------------------------------------------------------------
#define CONV_SMEM ((64 * 192 + 64 * 192 + 32 * 193) * 4)

__global__ __launch_bounds__(192) void conv_kernel(
    const float* __restrict__ qkv, const float* __restrict__ dw_w,
    const float* __restrict__ dw_b, const float* __restrict__ pw_w,
    const float* __restrict__ pw_b, float* __restrict__ att)
{
    extern __shared__ float smf[];
    float* vt   = smf;                       // [64][192] pixel-major
    float* pt   = smf + 64 * 192;            // depthwise out, same layout
    float* pw_s = smf + 2 * 64 * 192;        // [32][193] padded, pw_s[d][c]

    const int b = blockIdx.x;
    const int c = threadIdx.x;               // 0..191 channel

    // Load v_r tile: vt[p][c] (coalesced rows of 192 floats)
    const float* src = qkv + (size_t)b * 64 * QKVW + 576;
#pragma unroll
    for (int p = 0; p < 64; p++)
        vt[p * 192 + c] = src[(size_t)p * QKVW + c];

    // Stage pw_w transposed: pw_s[d][c] = pw_w[c][d], conflict-free via pad 193
#pragma unroll
    for (int i = 0; i < 32; i++) {
        int idx = i * 192 + c;               // linear over pw_w
        int cc = idx >> 5, d = idx & 31;
        pw_s[d * 193 + cc] = pw_w[idx];
    }
    __syncthreads();

    // ---- Depthwise 5x5 in registers ----
    float in[64];
#pragma unroll
    for (int p = 0; p < 64; p++) in[p] = vt[p * 192 + c];

    float w[25];
#pragma unroll
    for (int i = 0; i < 25; i++) w[i] = dw_w[c * 25 + i];
    const float db = dw_b[c];

#pragma unroll
    for (int p = 0; p < 64; p++) {
        const int y = p >> 3, x = p & 7;
        float a = db;
#pragma unroll
        for (int ky = 0; ky < 5; ky++) {
            const int yy = y + ky - 2;
            if (yy < 0 || yy > 7) continue;
#pragma unroll
            for (int kx = 0; kx < 5; kx++) {
                const int xx = x + kx - 2;
                if (xx < 0 || xx > 7) continue;
                a += in[yy * 8 + xx] * w[ky * 5 + kx];
            }
        }
        pt[p * 192 + c] = a;
    }
    __syncthreads();

    // ---- Grouped 1x1 (6 groups of 32) ----
    float wv[32];
#pragma unroll
    for (int d = 0; d < 32; d++) wv[d] = pw_s[d * 193 + c];
    const float pb = pw_b[c];
    const int g32 = (c >> 5) << 5;           // group base (warp-uniform)

    float* dst = att + (size_t)b * 64 * CDIM;
#pragma unroll
    for (int p = 0; p < 64; p++) {
        const float4* pr = (const float4*)(pt + p * 192 + g32);
        float a = pb;
#pragma unroll
        for (int d4 = 0; d4 < 8; d4++) {
            float4 v = pr[d4];               // warp-broadcast LDS.128
            a += v.x * wv[d4 * 4 + 0] + v.y * wv[d4 * 4 + 1]
               + v.z * wv[d4 * 4 + 2] + v.w * wv[d4 * 4 + 3];
        }
        dst[p * 192 + c] += a;
    }
}

// ---------------------------------------------------------------------------
extern "C" void kernel_launch(void* const* d_in, const int* in_sizes, int n_in,
                              void* d_out, int out_size)
{
    const float* x      = (const float*)d_in[0];
    const float* wq     = (const float*)d_in[1];
    const float* bq     = (const float*)d_in[2];
    const float* wkv    = (const float*)d_in[3];
    const float* bkv    = (const float*)d_in[4];
    const float* rpb    = (const float*)d_in[5];
    const int*   relidx = (const int*)  d_in[6];
    const float* dw_w   = (const float*)d_in[7];
    const float* dw_b   = (const float*)d_in[8];
    const float* pw_w   = (const float*)d_in[9];
    const float* pw_b   = (const float*)d_in[10];
    const float* proj_w = (const float*)d_in[11];
    const float* proj_b = (const float*)d_in[12];
    float* out = (float*)d_out;

    float *qkv, *att, *biasc, *bmat;
    __nv_bfloat16 *ah, *al, *ath, *atl, *wh, *wl, *pwh, *pwl;
    cudaGetSymbolAddress((void**)&qkv,  g_qkv);
    cudaGetSymbolAddress((void**)&att,  g_att);
    cudaGetSymbolAddress((void**)&ah,   g_ah);
    cudaGetSymbolAddress((void**)&al,   g_al);
    cudaGetSymbolAddress((void**)&ath,  g_ath);
    cudaGetSymbolAddress((void**)&atl,  g_atl);
    cudaGetSymbolAddress((void**)&wh,   g_wh);
    cudaGetSymbolAddress((void**)&wl,   g_wl);
    cudaGetSymbolAddress((void**)&pwh,  g_pwh);
    cudaGetSymbolAddress((void**)&pwl,  g_pwl);
    cudaGetSymbolAddress((void**)&biasc, g_bias);
    cudaGetSymbolAddress((void**)&bmat, g_bmat);

    cudaFuncSetAttribute(gemm_tc_kernel,
                         cudaFuncAttributeMaxDynamicSharedMemorySize, GEMM_SMEM);
    cudaFuncSetAttribute(conv_kernel,
                         cudaFuncAttributeMaxDynamicSharedMemorySize, CONV_SMEM);

    const int n4 = MROWS * KDIM / 4;

    // 0) weight prep (incl. bias matrices) + input split
    prep_w_kernel<<<(768 * 192 + 192 * 192 + 255) / 256, 256>>>(
        wq, wkv, bq, bkv, proj_w, rpb, relidx);
    split_kernel<<<(n4 + 255) / 256, 256>>>(x, ah, al, n4);

    // 1) fused q|k|v|v_r GEMM -> g_qkv
    gemm_tc_kernel<<<dim3(QKVW / 64, MROWS / 64), 128, GEMM_SMEM>>>(
        ah, al, wh, wl, biasc, qkv, QKVW);

    // 2) attention -> g_att
    attn_kernel<<<BATCH * NHEAD, 128>>>(qkv, bmat, att);

    // 3) conv branch accumulates into g_att
    conv_kernel<<<BATCH, 192, CONV_SMEM>>>(qkv, dw_w, dw_b, pw_w, pw_b, att);

    // 4) split attention output, then proj GEMM -> d_out
    split_kernel<<<(n4 + 255) / 256, 256>>>(att, ath, atl, n4);
    gemm_tc_kernel<<<dim3(CDIM / 64, MROWS / 64), 128, GEMM_SMEM>>>(
        ath, atl, pwh, pwl, proj_b, out, CDIM);
}

// round 7
// speedup vs baseline: 4.3139x; 1.3723x over previous
#include <cuda_runtime.h>
#include <cuda_bf16.h>
#include <cstdint>
#include <cstddef>

// Problem constants
#define BATCH 4096
#define NTOK 64
#define CDIM 192
#define NHEAD 6
#define HDIM 32
#define MROWS (BATCH * NTOK)   // 262144
#define QKVW 768               // q(192) + k(192) + v(192) + v_r(192)
#define KDIM 192

// ---------------------------------------------------------------------------
// Device scratch (no allocations allowed)
// ---------------------------------------------------------------------------
__device__ float g_qkv[(size_t)MROWS * QKVW];          // 805 MB
__device__ float g_att[(size_t)MROWS * CDIM];          // 201 MB
__device__ __nv_bfloat16 g_ah[(size_t)MROWS * KDIM];
__device__ __nv_bfloat16 g_al[(size_t)MROWS * KDIM];
__device__ __nv_bfloat16 g_ath[(size_t)MROWS * KDIM];
__device__ __nv_bfloat16 g_atl[(size_t)MROWS * KDIM];
__device__ __nv_bfloat16 g_wh[768 * 192];              // qkv weights (N-major) hi
__device__ __nv_bfloat16 g_wl[768 * 192];
__device__ __nv_bfloat16 g_pwh[192 * 192];
__device__ __nv_bfloat16 g_pwl[192 * 192];
__device__ float g_bias[768];                          // concat(bq, bkv)
__device__ float g_bmat[NHEAD * NTOK * NTOK];          // precomputed rel-pos bias

// ---------------------------------------------------------------------------
// MMA helpers (portable on compute_103: ldmatrix + mma.sync are sm_80 features)
// ---------------------------------------------------------------------------
__device__ __forceinline__ uint32_t smem_u32(const void* p) {
    uint32_t a;
    asm("{ .reg .u64 t; cvta.to.shared.u64 t, %1; cvt.u32.u64 %0, t; }"
        : "=r"(a) : "l"(p));
    return a;
}

__device__ __forceinline__ void ldsm4(uint32_t addr, uint32_t r[4]) {
    asm volatile("ldmatrix.sync.aligned.m8n8.x4.shared.b16 {%0,%1,%2,%3}, [%4];"
        : "=r"(r[0]), "=r"(r[1]), "=r"(r[2]), "=r"(r[3]) : "r"(addr));
}

__device__ __forceinline__ void mma16816(float c[4], const uint32_t a[4],
                                         uint32_t b0, uint32_t b1) {
    asm volatile(
        "mma.sync.aligned.m16n8k16.row.col.f32.bf16.bf16.f32 "
        "{%0,%1,%2,%3}, {%4,%5,%6,%7}, {%8,%9}, {%0,%1,%2,%3};"
        : "+f"(c[0]), "+f"(c[1]), "+f"(c[2]), "+f"(c[3])
        : "r"(a[0]), "r"(a[1]), "r"(a[2]), "r"(a[3]), "r"(b0), "r"(b1));
}

__device__ __forceinline__ uint32_t packbf2(float a, float b) {
    __nv_bfloat162 t = __floats2bfloat162_rn(a, b);   // .x = a (low), .y = b
    return *(uint32_t*)&t;
}

// ---------------------------------------------------------------------------
// fp32 -> (bf16 hi, bf16 lo) split
// ---------------------------------------------------------------------------
__device__ __forceinline__ void bf16_split(float v, __nv_bfloat16& h, __nv_bfloat16& l) {
    h = __float2bfloat16(v);
    l = __float2bfloat16(v - __bfloat162float(h));
}

__global__ __launch_bounds__(256) void split_kernel(
    const float* __restrict__ in, __nv_bfloat16* __restrict__ hi,
    __nv_bfloat16* __restrict__ lo, int n4)
{
    int i = blockIdx.x * 256 + threadIdx.x;
    if (i >= n4) return;
    float4 v = ((const float4*)in)[i];
    __nv_bfloat16 h[4], l[4];
    bf16_split(v.x, h[0], l[0]);
    bf16_split(v.y, h[1], l[1]);
    bf16_split(v.z, h[2], l[2]);
    bf16_split(v.w, h[3], l[3]);
    ((uint64_t*)hi)[i] = *(const uint64_t*)h;
    ((uint64_t*)lo)[i] = *(const uint64_t*)l;
}

// Weights: transpose to N-major [n][k] and split; concat biases; bias matrices.
__global__ __launch_bounds__(256) void prep_w_kernel(
    const float* __restrict__ wq, const float* __restrict__ wkv,
    const float* __restrict__ bq, const float* __restrict__ bkv,
    const float* __restrict__ projw,
    const float* __restrict__ rpb, const int* __restrict__ relidx)
{
    int idx = blockIdx.x * 256 + threadIdx.x;
    if (idx < 768 * 192) {
        int n = idx / 192, k = idx % 192;
        float v = (n < 192) ? wq[k * 192 + n] : wkv[k * 576 + (n - 192)];
        bf16_split(v, g_wh[idx], g_wl[idx]);
    } else if (idx < 768 * 192 + 192 * 192) {
        int j = idx - 768 * 192;
        int n = j / 192, k = j % 192;
        bf16_split(projw[k * 192 + n], g_pwh[j], g_pwl[j]);
    }
    if (idx < 768) g_bias[idx] = (idx < 192) ? bq[idx] : bkv[idx - 192];
    if (idx < NTOK * NTOK) {
        int ri = relidx[idx];
#pragma unroll
        for (int h = 0; h < NHEAD; h++)
            g_bmat[h * (NTOK * NTOK) + idx] = rpb[ri * NHEAD + h];
    }
}

// ---------------------------------------------------------------------------
// HMMA GEMM (validated in R5/R6, unchanged)
// ---------------------------------------------------------------------------
#define LDSG 200
#define SM_AH 0
#define SM_AL (64 * LDSG)
#define SM_BH (128 * LDSG)
#define SM_BL (192 * LDSG)
#define GEMM_SMEM (256 * LDSG * 2)     // 102400 bytes

__global__ __launch_bounds__(128) void gemm_tc_kernel(
    const __nv_bfloat16* __restrict__ Ah, const __nv_bfloat16* __restrict__ Al,
    const __nv_bfloat16* __restrict__ Bh, const __nv_bfloat16* __restrict__ Bl,
    const float* __restrict__ bias, float* __restrict__ C, int ldc)
{
    extern __shared__ __nv_bfloat16 sm[];
    const int t = threadIdx.x;
    const int lane = t & 31;
    const int wid = t >> 5;
    const int wm = wid >> 1;
    const int wn = wid & 1;
    const int n0   = blockIdx.x * 64;
    const int row0 = blockIdx.y * 64;

#pragma unroll
    for (int it = 0; it < 24; it++) {
        int idx = it * 128 + t;
        int r = idx / 48;
        int k = (idx % 48) * 4;
        size_t g = (size_t)(row0 + r) * KDIM + k;
        int s = r * LDSG + k;
        *(uint64_t*)(sm + SM_AH + s) = *(const uint64_t*)(Ah + g);
        *(uint64_t*)(sm + SM_AL + s) = *(const uint64_t*)(Al + g);
    }
#pragma unroll
    for (int it = 0; it < 24; it++) {
        int idx = it * 128 + t;
        int r = idx / 48;
        int k = (idx % 48) * 4;
        size_t g = (size_t)(n0 + r) * KDIM + k;
        int s = r * LDSG + k;
        *(uint64_t*)(sm + SM_BH + s) = *(const uint64_t*)(Bh + g);
        *(uint64_t*)(sm + SM_BL + s) = *(const uint64_t*)(Bl + g);
    }
    __syncthreads();

    float acc[2][4][4];
#pragma unroll
    for (int i = 0; i < 2; i++)
#pragma unroll
        for (int j = 0; j < 4; j++)
#pragma unroll
            for (int e = 0; e < 4; e++) acc[i][j][e] = 0.0f;

    const uint32_t sbase = smem_u32(sm);
    const uint32_t aoff = (uint32_t)((wm * 32 + (lane & 15)) * LDSG + ((lane >> 4) << 3));
    const uint32_t boff = (uint32_t)((wn * 32 + (lane & 7) + ((lane >> 4) << 3)) * LDSG
                                     + (((lane >> 3) & 1) << 3));

#pragma unroll
    for (int pass = 0; pass < 3; pass++) {
        const uint32_t aBase = sbase + 2u * (pass == 1 ? SM_AL : SM_AH);
        const uint32_t bBase = sbase + 2u * (pass == 2 ? SM_BL : SM_BH);
#pragma unroll
        for (int ks = 0; ks < 12; ks++) {
            const uint32_t k0 = ks * 16;
            uint32_t a0[4], a1[4], b0[4], b1[4];
            ldsm4(aBase + (aoff + k0) * 2, a0);
            ldsm4(aBase + (aoff + 16 * LDSG + k0) * 2, a1);
            ldsm4(bBase + (boff + k0) * 2, b0);
            ldsm4(bBase + (boff + 16 * LDSG + k0) * 2, b1);

            mma16816(acc[0][0], a0, b0[0], b0[1]);
            mma16816(acc[0][1], a0, b0[2], b0[3]);
            mma16816(acc[0][2], a0, b1[0], b1[1]);
            mma16816(acc[0][3], a0, b1[2], b1[3]);
            mma16816(acc[1][0], a1, b0[0], b0[1]);
            mma16816(acc[1][1], a1, b0[2], b0[3]);
            mma16816(acc[1][2], a1, b1[0], b1[1]);
            mma16816(acc[1][3], a1, b1[2], b1[3]);
        }
    }

    const int r_base = row0 + wm * 32 + (lane >> 2);
    const int c_base = n0 + wn * 32 + (lane & 3) * 2;
#pragma unroll
    for (int nt = 0; nt < 4; nt++) {
        const int col = c_base + nt * 8;
        const float bv0 = bias[col];
        const float bv1 = bias[col + 1];
#pragma unroll
        for (int mt = 0; mt < 2; mt++) {
            const int r = r_base + mt * 16;
            float2 v0 = make_float2(acc[mt][nt][0] + bv0, acc[mt][nt][1] + bv1);
            float2 v1 = make_float2(acc[mt][nt][2] + bv0, acc[mt][nt][3] + bv1);
            *(float2*)(C + (size_t)r * ldc + col)       = v0;
            *(float2*)(C + (size_t)(r + 8) * ldc + col) = v1;
        }
    }
}

// ---------------------------------------------------------------------------
// HMMA attention: one block per (batch, head), 128 threads = 4 warps.
// Warp w owns rows 16w..16w+15. QK^T and PV both on tensor cores with
// bf16 hi/lo 3-pass splits; softmax in registers (shfl_xor over 4-lane group).
// ---------------------------------------------------------------------------
__global__ __launch_bounds__(128) void attn_kernel(
    const float* __restrict__ qkv, const float* __restrict__ bmat,
    float* __restrict__ out)
{
    const int h = blockIdx.x % NHEAD;
    const int b = blockIdx.x / NHEAD;
    const int t = threadIdx.x;
    const int lane = t & 31;
    const int w = t >> 5;

    __shared__ __nv_bfloat16 qh[64][40], ql[64][40];
    __shared__ __nv_bfloat16 kh[64][40], kl[64][40];
    __shared__ __nv_bfloat16 vth[32][72], vtl[32][72];  // [d][token]

    // ---- load + split ----
    {
        const int n = t >> 1;
        const int half = t & 1;
        const float scale = 0.1767766952966369f;  // 1/sqrt(32)
        const float* base = qkv + (size_t)(b * 64 + n) * QKVW + h * HDIM + half * 16;
#pragma unroll
        for (int i = 0; i < 4; i++) {
            float4 qv = *(const float4*)(base + i * 4);
            float4 kv = *(const float4*)(base + 192 + i * 4);
            float4 vv = *(const float4*)(base + 384 + i * 4);
            const float qf[4] = {qv.x * scale, qv.y * scale, qv.z * scale, qv.w * scale};
            const float kf[4] = {kv.x, kv.y, kv.z, kv.w};
            const float vf[4] = {vv.x, vv.y, vv.z, vv.w};
            const int c0 = half * 16 + i * 4;
#pragma unroll
            for (int e = 0; e < 4; e++) {
                __nv_bfloat16 hh, ll;
                bf16_split(qf[e], hh, ll);
                qh[n][c0 + e] = hh; ql[n][c0 + e] = ll;
                bf16_split(kf[e], hh, ll);
                kh[n][c0 + e] = hh; kl[n][c0 + e] = ll;
                bf16_split(vf[e], hh, ll);
                vth[c0 + e][n] = hh; vtl[c0 + e][n] = ll;
            }
        }
    }
    __syncthreads();

    // ---- QK^T ----
    float s[8][4];
#pragma unroll
    for (int j = 0; j < 8; j++)
#pragma unroll
        for (int e = 0; e < 4; e++) s[j][e] = 0.0f;

    const uint32_t qhB = smem_u32(&qh[0][0]);
    const uint32_t qlB = smem_u32(&ql[0][0]);
    const uint32_t khB = smem_u32(&kh[0][0]);
    const uint32_t klB = smem_u32(&kl[0][0]);
    const uint32_t aoff = (uint32_t)((16 * w + (lane & 15)) * 40 + ((lane >> 4) << 3));
    const uint32_t boff = (uint32_t)(((lane & 7) + ((lane >> 4) << 3)) * 40
                                     + (((lane >> 3) & 1) << 3));

#pragma unroll
    for (int pass = 0; pass < 3; pass++) {
        const uint32_t aB = (pass == 1) ? qlB : qhB;
        const uint32_t bB = (pass == 2) ? klB : khB;
#pragma unroll
        for (int ks = 0; ks < 2; ks++) {
            uint32_t A[4];
            ldsm4(aB + (aoff + ks * 16) * 2, A);
#pragma unroll
            for (int nt = 0; nt < 4; nt++) {
                uint32_t B[4];
                ldsm4(bB + (boff + nt * 16 * 40 + ks * 16) * 2, B);
                mma16816(s[2 * nt],     A, B[0], B[1]);
                mma16816(s[2 * nt + 1], A, B[2], B[3]);
            }
        }
    }

    // ---- bias + softmax (rows r0 = 16w + lane/4, r1 = r0+8) ----
    const int r0 = 16 * w + (lane >> 2);
    const int cb = 2 * (lane & 3);
    const float* bm = bmat + h * 4096;
#pragma unroll
    for (int j = 0; j < 8; j++) {
        float2 b0 = *(const float2*)(bm + r0 * 64 + 8 * j + cb);
        float2 b1 = *(const float2*)(bm + (r0 + 8) * 64 + 8 * j + cb);
        s[j][0] += b0.x; s[j][1] += b0.y;
        s[j][2] += b1.x; s[j][3] += b1.y;
    }

    float mx0 = -1e30f, mx1 = -1e30f;
#pragma unroll
    for (int j = 0; j < 8; j++) {
        mx0 = fmaxf(mx0, fmaxf(s[j][0], s[j][1]));
        mx1 = fmaxf(mx1, fmaxf(s[j][2], s[j][3]));
    }
    mx0 = fmaxf(mx0, __shfl_xor_sync(0xffffffffu, mx0, 1));
    mx0 = fmaxf(mx0, __shfl_xor_sync(0xffffffffu, mx0, 2));
    mx1 = fmaxf(mx1, __shfl_xor_sync(0xffffffffu, mx1, 1));
    mx1 = fmaxf(mx1, __shfl_xor_sync(0xffffffffu, mx1, 2));

    float sum0 = 0.0f, sum1 = 0.0f;
#pragma unroll
    for (int j = 0; j < 8; j++) {
        s[j][0] = __expf(s[j][0] - mx0); sum0 += s[j][0];
        s[j][1] = __expf(s[j][1] - mx0); sum0 += s[j][1];
        s[j][2] = __expf(s[j][2] - mx1); sum1 += s[j][2];
        s[j][3] = __expf(s[j][3] - mx1); sum1 += s[j][3];
    }
    sum0 += __shfl_xor_sync(0xffffffffu, sum0, 1);
    sum0 += __shfl_xor_sync(0xffffffffu, sum0, 2);
    sum1 += __shfl_xor_sync(0xffffffffu, sum1, 1);
    sum1 += __shfl_xor_sync(0xffffffffu, sum1, 2);
    const float inv0 = 1.0f / sum0;
    const float inv1 = 1.0f / sum1;

    // ---- P -> bf16 hi/lo A-fragments in registers ----
    uint32_t ph[4][4], pl[4][4];
#pragma unroll
    for (int ks = 0; ks < 4; ks++) {
        const int j0 = 2 * ks, j1 = 2 * ks + 1;
        float p[8] = { s[j0][0] * inv0, s[j0][1] * inv0,
                       s[j0][2] * inv1, s[j0][3] * inv1,
                       s[j1][0] * inv0, s[j1][1] * inv0,
                       s[j1][2] * inv1, s[j1][3] * inv1 };
        float hi[8], lo[8];
#pragma unroll
        for (int e = 0; e < 8; e++) {
            __nv_bfloat16 hh = __float2bfloat16(p[e]);
            hi[e] = __bfloat162float(hh);
            lo[e] = p[e] - hi[e];
        }
        ph[ks][0] = packbf2(hi[0], hi[1]); pl[ks][0] = packbf2(lo[0], lo[1]);
        ph[ks][1] = packbf2(hi[2], hi[3]); pl[ks][1] = packbf2(lo[2], lo[3]);
        ph[ks][2] = packbf2(hi[4], hi[5]); pl[ks][2] = packbf2(lo[4], lo[5]);
        ph[ks][3] = packbf2(hi[6], hi[7]); pl[ks][3] = packbf2(lo[6], lo[7]);
    }

    // ---- PV ----
    float o[4][4];
#pragma unroll
    for (int j = 0; j < 4; j++)
#pragma unroll
        for (int e = 0; e < 4; e++) o[j][e] = 0.0f;

    const uint32_t vhB = smem_u32(&vth[0][0]);
    const uint32_t vlB = smem_u32(&vtl[0][0]);
    const uint32_t vrow = (uint32_t)((lane & 7) + ((lane >> 4) << 3));
    const uint32_t vcol = (uint32_t)(((lane >> 3) & 1) << 3);

#pragma unroll
    for (int pass = 0; pass < 3; pass++) {
        const uint32_t (*A)[4] = (pass == 1) ? pl : ph;
        const uint32_t vB = (pass == 2) ? vlB : vhB;
#pragma unroll
        for (int ks = 0; ks < 4; ks++) {
            uint32_t B0[4], B1[4];
            ldsm4(vB + ((vrow) * 72 + ks * 16 + vcol) * 2, B0);
            ldsm4(vB + ((vrow + 16) * 72 + ks * 16 + vcol) * 2, B1);
            mma16816(o[0], A[ks], B0[0], B0[1]);
            mma16816(o[1], A[ks], B0[2], B0[3]);
            mma16816(o[2], A[ks], B1[0], B1[1]);
            mma16816(o[3], A[ks], B1[2], B1[3]);
        }
    }

    // ---- store ----
    float* op = out + (size_t)(b * 64) * CDIM + h * HDIM;
#pragma unroll
    for (int j = 0; j < 4; j++) {
        const int d = 8 * j + cb;
        *(float2*)(op + (size_t)r0 * CDIM + d)       = make_float2(o[j][0], o[j][1]);
        *(float2*)(op + (size_t)(r0 + 8) * CDIM + d) = make_float2(o[j][2], o[j][3]);
    }
}

// ---------------------------------------------------------------------------
// Positional conv branch (validated in R6, unchanged)
// ---------------------------------------------------------------------------
#define CONV_SMEM ((64 * 192 + 64 * 192 + 32 * 193) * 4)

__global__ __launch_bounds__(192) void conv_kernel(
    const float* __restrict__ qkv, const float* __restrict__ dw_w,
    const float* __restrict__ dw_b, const float* __restrict__ pw_w,
    const float* __restrict__ pw_b, float* __restrict__ att)
{
    extern __shared__ float smf[];
    float* vt   = smf;
    float* pt   = smf + 64 * 192;
    float* pw_s = smf + 2 * 64 * 192;

    const int b = blockIdx.x;
    const int c = threadIdx.x;

    const float* src = qkv + (size_t)b * 64 * QKVW + 576;
#pragma unroll
    for (int p = 0; p < 64; p++)
        vt[p * 192 + c] = src[(size_t)p * QKVW + c];

#pragma unroll
    for (int i = 0; i < 32; i++) {
        int idx = i * 192 + c;
        int cc = idx >> 5, d = idx & 31;
        pw_s[d * 193 + cc] = pw_w[idx];
    }
    __syncthreads();

    float in[64];
#pragma unroll
    for (int p = 0; p < 64; p++) in[p] = vt[p * 192 + c];

    float w[25];
#pragma unroll
    for (int i = 0; i < 25; i++) w[i] = dw_w[c * 25 + i];
    const float db = dw_b[c];

#pragma unroll
    for (int p = 0; p < 64; p++) {
        const int y = p >> 3, x = p & 7;
        float a = db;
#pragma unroll
        for (int ky = 0; ky < 5; ky++) {
            const int yy = y + ky - 2;
            if (yy < 0 || yy > 7) continue;
#pragma unroll
            for (int kx = 0; kx < 5; kx++) {
                const int xx = x + kx - 2;
                if (xx < 0 || xx > 7) continue;
                a += in[yy * 8 + xx] * w[ky * 5 + kx];
            }
        }
        pt[p * 192 + c] = a;
    }
    __syncthreads();

    float wv[32];
#pragma unroll
    for (int d = 0; d < 32; d++) wv[d] = pw_s[d * 193 + c];
    const float pb = pw_b[c];
    const int g32 = (c >> 5) << 5;

    float* dst = att + (size_t)b * 64 * CDIM;
#pragma unroll
    for (int p = 0; p < 64; p++) {
        const float4* pr = (const float4*)(pt + p * 192 + g32);
        float a = pb;
#pragma unroll
        for (int d4 = 0; d4 < 8; d4++) {
            float4 v = pr[d4];
            a += v.x * wv[d4 * 4 + 0] + v.y * wv[d4 * 4 + 1]
               + v.z * wv[d4 * 4 + 2] + v.w * wv[d4 * 4 + 3];
        }
        dst[p * 192 + c] += a;
    }
}

// ---------------------------------------------------------------------------
extern "C" void kernel_launch(void* const* d_in, const int* in_sizes, int n_in,
                              void* d_out, int out_size)
{
    const float* x      = (const float*)d_in[0];
    const float* wq     = (const float*)d_in[1];
    const float* bq     = (const float*)d_in[2];
    const float* wkv    = (const float*)d_in[3];
    const float* bkv    = (const float*)d_in[4];
    const float* rpb    = (const float*)d_in[5];
    const int*   relidx = (const int*)  d_in[6];
    const float* dw_w   = (const float*)d_in[7];
    const float* dw_b   = (const float*)d_in[8];
    const float* pw_w   = (const float*)d_in[9];
    const float* pw_b   = (const float*)d_in[10];
    const float* proj_w = (const float*)d_in[11];
    const float* proj_b = (const float*)d_in[12];
    float* out = (float*)d_out;

    float *qkv, *att, *biasc, *bmat;
    __nv_bfloat16 *ah, *al, *ath, *atl, *wh, *wl, *pwh, *pwl;
    cudaGetSymbolAddress((void**)&qkv,  g_qkv);
    cudaGetSymbolAddress((void**)&att,  g_att);
    cudaGetSymbolAddress((void**)&ah,   g_ah);
    cudaGetSymbolAddress((void**)&al,   g_al);
    cudaGetSymbolAddress((void**)&ath,  g_ath);
    cudaGetSymbolAddress((void**)&atl,  g_atl);
    cudaGetSymbolAddress((void**)&wh,   g_wh);
    cudaGetSymbolAddress((void**)&wl,   g_wl);
    cudaGetSymbolAddress((void**)&pwh,  g_pwh);
    cudaGetSymbolAddress((void**)&pwl,  g_pwl);
    cudaGetSymbolAddress((void**)&biasc, g_bias);
    cudaGetSymbolAddress((void**)&bmat, g_bmat);

    cudaFuncSetAttribute(gemm_tc_kernel,
                         cudaFuncAttributeMaxDynamicSharedMemorySize, GEMM_SMEM);
    cudaFuncSetAttribute(conv_kernel,
                         cudaFuncAttributeMaxDynamicSharedMemorySize, CONV_SMEM);

    const int n4 = MROWS * KDIM / 4;

    // 0) weight prep (incl. bias matrices) + input split
    prep_w_kernel<<<(768 * 192 + 192 * 192 + 255) / 256, 256>>>(
        wq, wkv, bq, bkv, proj_w, rpb, relidx);
    split_kernel<<<(n4 + 255) / 256, 256>>>(x, ah, al, n4);

    // 1) fused q|k|v|v_r GEMM -> g_qkv
    gemm_tc_kernel<<<dim3(QKVW / 64, MROWS / 64), 128, GEMM_SMEM>>>(
        ah, al, wh, wl, biasc, qkv, QKVW);

    // 2) attention -> g_att (HMMA)
    attn_kernel<<<BATCH * NHEAD, 128>>>(qkv, bmat, att);

    // 3) conv branch accumulates into g_att
    conv_kernel<<<BATCH, 192, CONV_SMEM>>>(qkv, dw_w, dw_b, pw_w, pw_b, att);

    // 4) split attention output, then proj GEMM -> d_out
    split_kernel<<<(n4 + 255) / 256, 256>>>(att, ath, atl, n4);
    gemm_tc_kernel<<<dim3(CDIM / 64, MROWS / 64), 128, GEMM_SMEM>>>(
        ath, atl, pwh, pwl, proj_b, out, CDIM);
}